// round 15
// baseline (speedup 1.0000x reference)
#include <cuda_runtime.h>
#include <cuda_bf16.h>
#include <math.h>

// ---------------- problem constants ----------------
#define BATCH 8
#define T 4096
#define BT (BATCH*T)          // 32768
#define DIM 768
#define EMB 768
#define MFEAT 384
#define KQV_OUT 2304
#define PRM_SCALE 0.051031036307982884f   // 1/sqrt(384)
#define EPS 1e-8f

// ---------------- scratch (device globals) ----------------
__device__ float g_o1  [(size_t)BT*768];
__device__ float g_kqv [(size_t)BT*KQV_OUT];
__device__ float g_kpq [(size_t)2*BT*MFEAT];      // kp then qp
__device__ float g_xd  [2*BT];                    // xdk then xdq
__device__ float g_kpart[BATCH*32*MFEAT];
__device__ float g_ksum [BATCH*MFEAT];
__device__ float g_kptvp[(size_t)BATCH*4*EMB*MFEAT];
__device__ float g_kptv [(size_t)BATCH*EMB*MFEAT];
__device__ float g_dinv [BT];
__device__ float g_y   [(size_t)BT*768];

// ---------------- packed f32x2 FMA (Blackwell FFMA2; ptxas never emits this) --
typedef unsigned long long u64t;
#define FMA_X2(d, a, b) asm("fma.rn.f32x2 %0, %1, %2, %0;" : "+l"(d) : "l"(a), "l"(b))
__device__ __forceinline__ float lo32(u64t v) { return __uint_as_float((unsigned)v); }
__device__ __forceinline__ float hi32(u64t v) { return __uint_as_float((unsigned)(v >> 32)); }

// ---------------- generic NT SGEMM: C = A (MxK, row-major) * B^T (B is NxK row-major)
// tile 256x64x16, 256 threads, 8x8 per thread, rows packed in pairs (FFMA2)
#define TM 256
#define TN 64
#define TK 16

#define MODE_NONE 0
#define MODE_EXP  1   // v = exp(acc - rowv[row]) * scale
#define MODE_RSC  2   // v = acc * rowv[row]

__global__ __launch_bounds__(256, 2)
void gemm_nt(const float* __restrict__ A, int lda, long long aZoff,
             const float* __restrict__ Bm, long long bZoff, int K,
             float* __restrict__ C, int ldc, int cs, int czCo, long long cZoff,
             const float* __restrict__ bias,
             const float* __restrict__ rowv, int rvz,
             int mode, float scale)
{
    const int z = blockIdx.z;
    const float* Ab = A + (size_t)z * aZoff;
    const float* Bb = Bm + (size_t)z * bZoff;
    float*       Cb = C + (size_t)z * cZoff;

    const int rowBase = blockIdx.y * TM;
    const int colBase = blockIdx.x * TN;

    __shared__ __align__(16) float As [TK][TM + 4];       // stride 260 floats (16B mult)
    __shared__ __align__(16) float BsD[TK][2*TN + 4];     // duplicated {b,b}; stride 132

    const int tid = threadIdx.x;
    const int tx = tid & 7;        // n-group: cols tx*4.. and tx*4+32..
    const int ty = tid >> 3;       // m-group: rows ty*8..ty*8+7

    const int ar  = tid >> 2;      // A stage: base row, rows ar + i*64
    const int ac4 = tid & 3;       // A stage: f4 k-col
    const int br  = tid >> 2;      // B stage: n row (0..63)
    const int bc4 = tid & 3;       // B stage: f4 k-col

    float4 stA[4];
    float4 stB;

    u64t accP[4][8];               // [row-pair i2][col j]
#pragma unroll
    for (int i = 0; i < 4; i++)
#pragma unroll
        for (int j = 0; j < 8; j++) accP[i][j] = 0ull;

    const int nK = K / TK;

    // prologue loads
#pragma unroll
    for (int i = 0; i < 4; i++) {
        int r = ar + i * 64;
        stA[i] = *reinterpret_cast<const float4*>(&Ab[(size_t)(rowBase + r) * lda + ac4 * 4]);
    }
    stB = *reinterpret_cast<const float4*>(&Bb[(size_t)(colBase + br) * K + bc4 * 4]);

    int k0 = 0;
    for (int kb = 0; kb < nK; ++kb) {
        // stage A (transposed scatter)
#pragma unroll
        for (int i = 0; i < 4; i++) {
            int r = ar + i * 64;
            As[ac4 * 4 + 0][r] = stA[i].x;
            As[ac4 * 4 + 1][r] = stA[i].y;
            As[ac4 * 4 + 2][r] = stA[i].z;
            As[ac4 * 4 + 3][r] = stA[i].w;
        }
        // stage B duplicated: BsD[k][2n]=BsD[k][2n+1]=b
        *reinterpret_cast<float2*>(&BsD[bc4 * 4 + 0][2 * br]) = make_float2(stB.x, stB.x);
        *reinterpret_cast<float2*>(&BsD[bc4 * 4 + 1][2 * br]) = make_float2(stB.y, stB.y);
        *reinterpret_cast<float2*>(&BsD[bc4 * 4 + 2][2 * br]) = make_float2(stB.z, stB.z);
        *reinterpret_cast<float2*>(&BsD[bc4 * 4 + 3][2 * br]) = make_float2(stB.w, stB.w);
        __syncthreads();

        if (kb + 1 < nK) {
            k0 += TK;
#pragma unroll
            for (int i = 0; i < 4; i++) {
                int r = ar + i * 64;
                stA[i] = *reinterpret_cast<const float4*>(&Ab[(size_t)(rowBase + r) * lda + k0 + ac4 * 4]);
            }
            stB = *reinterpret_cast<const float4*>(&Bb[(size_t)(colBase + br) * K + k0 + bc4 * 4]);
        }

#pragma unroll
        for (int kk = 0; kk < TK; ++kk) {
            ulonglong2 a01 = *reinterpret_cast<const ulonglong2*>(&As[kk][ty * 8]);
            ulonglong2 a23 = *reinterpret_cast<const ulonglong2*>(&As[kk][ty * 8 + 4]);
            ulonglong2 b01 = *reinterpret_cast<const ulonglong2*>(&BsD[kk][tx * 8]);
            ulonglong2 b23 = *reinterpret_cast<const ulonglong2*>(&BsD[kk][tx * 8 + 4]);
            ulonglong2 b45 = *reinterpret_cast<const ulonglong2*>(&BsD[kk][tx * 8 + 64]);
            ulonglong2 b67 = *reinterpret_cast<const ulonglong2*>(&BsD[kk][tx * 8 + 68]);
            u64t pa[4] = {a01.x, a01.y, a23.x, a23.y};
            u64t pb[8] = {b01.x, b01.y, b23.x, b23.y, b45.x, b45.y, b67.x, b67.y};
#pragma unroll
            for (int i2 = 0; i2 < 4; i2++)
#pragma unroll
                for (int j = 0; j < 8; j++)
                    FMA_X2(accP[i2][j], pa[i2], pb[j]);
        }
        __syncthreads();
    }

    // unpack pairs -> c[8][8]
    float c[8][8];
#pragma unroll
    for (int i2 = 0; i2 < 4; i2++)
#pragma unroll
        for (int j = 0; j < 8; j++) {
            c[2 * i2 + 0][j] = lo32(accP[i2][j]);
            c[2 * i2 + 1][j] = hi32(accP[i2][j]);
        }

    const int row0 = rowBase + ty * 8;
    const int c0 = colBase + tx * 4;
    const int c1 = c0 + 32;

    if (cs == 1) {
#pragma unroll
        for (int i = 0; i < 8; i++) {
            float rv = 0.f;
            if (mode != MODE_NONE) rv = rowv[(size_t)z * rvz + row0 + i];
            float4 v0, v1;
            if (mode == MODE_EXP) {
                v0.x = expf(c[i][0] - rv) * scale; v0.y = expf(c[i][1] - rv) * scale;
                v0.z = expf(c[i][2] - rv) * scale; v0.w = expf(c[i][3] - rv) * scale;
                v1.x = expf(c[i][4] - rv) * scale; v1.y = expf(c[i][5] - rv) * scale;
                v1.z = expf(c[i][6] - rv) * scale; v1.w = expf(c[i][7] - rv) * scale;
            } else if (mode == MODE_RSC) {
                v0.x = c[i][0] * rv; v0.y = c[i][1] * rv; v0.z = c[i][2] * rv; v0.w = c[i][3] * rv;
                v1.x = c[i][4] * rv; v1.y = c[i][5] * rv; v1.z = c[i][6] * rv; v1.w = c[i][7] * rv;
            } else {
                v0 = make_float4(c[i][0], c[i][1], c[i][2], c[i][3]);
                v1 = make_float4(c[i][4], c[i][5], c[i][6], c[i][7]);
            }
            size_t rb = (size_t)(row0 + i) * ldc;
            *reinterpret_cast<float4*>(&Cb[rb + c0]) = v0;
            *reinterpret_cast<float4*>(&Cb[rb + c1]) = v1;
        }
    } else {
        // scattered monarch-permutation store: colMem = col*cs + z*czCo
#pragma unroll
        for (int i = 0; i < 8; i++) {
            size_t rb = (size_t)(row0 + i) * ldc;
#pragma unroll
            for (int j = 0; j < 4; j++) {
                int cm = (c0 + j) * cs + z * czCo;
                float v = c[i][j];
                if (bias) v += bias[cm];
                Cb[rb + cm] = v;
            }
#pragma unroll
            for (int j = 0; j < 4; j++) {
                int cm = (c1 + j) * cs + z * czCo;
                float v = c[i][4 + j];
                if (bias) v += bias[cm];
                Cb[rb + cm] = v;
            }
        }
    }
}

// ---------------- TN SGEMM for kptv (split-K=4): part[z][n,m] = sum_t v[t,n]*kp[t,m]
__global__ __launch_bounds__(256, 2)
void gemm_tn_kptv(const float* __restrict__ Vg,   // kqv + 1536
                  const float* __restrict__ KPg,  // kp
                  float* __restrict__ part)
{
    const int z = blockIdx.z;
    const int b = z >> 2, s = z & 3;
    const float* Ab = Vg  + ((size_t)b * T + (size_t)s * 1024) * KQV_OUT;
    const float* Bb = KPg + ((size_t)b * T + (size_t)s * 1024) * MFEAT;
    float*       Cb = part + (size_t)z * EMB * MFEAT;

    const int nBase = blockIdx.y * TM;
    const int mBase = blockIdx.x * TN;

    __shared__ __align__(16) float As [TK][TM + 4];
    __shared__ __align__(16) float BsD[TK][2*TN + 4];

    const int tid = threadIdx.x;
    const int tx = tid & 7;
    const int ty = tid >> 3;

    const int a_tk0 = tid >> 6;
    const int a_n4  = tid & 63;
    const int b_tk  = tid >> 4;
    const int b_m4  = tid & 15;

    float4 stA[4];
    float4 stB;

    u64t accP[4][8];
#pragma unroll
    for (int i = 0; i < 4; i++)
#pragma unroll
        for (int j = 0; j < 8; j++) accP[i][j] = 0ull;

    const int nK = 1024 / TK;

#pragma unroll
    for (int i = 0; i < 4; i++) {
        int tk = a_tk0 + i * 4;
        stA[i] = *reinterpret_cast<const float4*>(&Ab[(size_t)tk * KQV_OUT + nBase + a_n4 * 4]);
    }
    stB = *reinterpret_cast<const float4*>(&Bb[(size_t)b_tk * MFEAT + mBase + b_m4 * 4]);

    int k0 = 0;
    for (int kb = 0; kb < nK; ++kb) {
#pragma unroll
        for (int i = 0; i < 4; i++) {
            int tk = a_tk0 + i * 4;
            *reinterpret_cast<float4*>(&As[tk][a_n4 * 4]) = stA[i];
        }
        *reinterpret_cast<float4*>(&BsD[b_tk][b_m4 * 8])     = make_float4(stB.x, stB.x, stB.y, stB.y);
        *reinterpret_cast<float4*>(&BsD[b_tk][b_m4 * 8 + 4]) = make_float4(stB.z, stB.z, stB.w, stB.w);
        __syncthreads();

        if (kb + 1 < nK) {
            k0 += TK;
#pragma unroll
            for (int i = 0; i < 4; i++) {
                int tk = k0 + a_tk0 + i * 4;
                stA[i] = *reinterpret_cast<const float4*>(&Ab[(size_t)tk * KQV_OUT + nBase + a_n4 * 4]);
            }
            stB = *reinterpret_cast<const float4*>(&Bb[(size_t)(k0 + b_tk) * MFEAT + mBase + b_m4 * 4]);
        }

#pragma unroll
        for (int kk = 0; kk < TK; ++kk) {
            ulonglong2 a01 = *reinterpret_cast<const ulonglong2*>(&As[kk][ty * 8]);
            ulonglong2 a23 = *reinterpret_cast<const ulonglong2*>(&As[kk][ty * 8 + 4]);
            ulonglong2 b01 = *reinterpret_cast<const ulonglong2*>(&BsD[kk][tx * 8]);
            ulonglong2 b23 = *reinterpret_cast<const ulonglong2*>(&BsD[kk][tx * 8 + 4]);
            ulonglong2 b45 = *reinterpret_cast<const ulonglong2*>(&BsD[kk][tx * 8 + 64]);
            ulonglong2 b67 = *reinterpret_cast<const ulonglong2*>(&BsD[kk][tx * 8 + 68]);
            u64t pa[4] = {a01.x, a01.y, a23.x, a23.y};
            u64t pb[8] = {b01.x, b01.y, b23.x, b23.y, b45.x, b45.y, b67.x, b67.y};
#pragma unroll
            for (int i2 = 0; i2 < 4; i2++)
#pragma unroll
                for (int j = 0; j < 8; j++)
                    FMA_X2(accP[i2][j], pa[i2], pb[j]);
        }
        __syncthreads();
    }

    const int row0 = nBase + ty * 8;
    const int c0 = mBase + tx * 4;
#pragma unroll
    for (int i2 = 0; i2 < 4; i2++)
#pragma unroll
        for (int h = 0; h < 2; h++) {
            int i = 2 * i2 + h;
            float4 v0, v1;
            if (h == 0) {
                v0 = make_float4(lo32(accP[i2][0]), lo32(accP[i2][1]), lo32(accP[i2][2]), lo32(accP[i2][3]));
                v1 = make_float4(lo32(accP[i2][4]), lo32(accP[i2][5]), lo32(accP[i2][6]), lo32(accP[i2][7]));
            } else {
                v0 = make_float4(hi32(accP[i2][0]), hi32(accP[i2][1]), hi32(accP[i2][2]), hi32(accP[i2][3]));
                v1 = make_float4(hi32(accP[i2][4]), hi32(accP[i2][5]), hi32(accP[i2][6]), hi32(accP[i2][7]));
            }
            size_t rb = (size_t)(row0 + i) * MFEAT;
            *reinterpret_cast<float4*>(&Cb[rb + c0])      = v0;
            *reinterpret_cast<float4*>(&Cb[rb + c0 + 32]) = v1;
        }
}

__global__ void kptv_reduce(const float* __restrict__ part, float* __restrict__ kptv)
{
    size_t i = (size_t)blockIdx.x * blockDim.x + threadIdx.x;
    const size_t N = (size_t)BATCH * EMB * MFEAT;
    if (i >= N) return;
    int b = (int)(i / (EMB * MFEAT));
    size_t off = i - (size_t)b * EMB * MFEAT;
    const float* p = part + (size_t)b * 4 * EMB * MFEAT + off;
    kptv[i] = p[0] + p[(size_t)EMB * MFEAT] + p[(size_t)2 * EMB * MFEAT] + p[(size_t)3 * EMB * MFEAT];
}

// ---------------- helper kernels ----------------
__global__ void xd_kernel(const float* __restrict__ kqv, float* __restrict__ xd)
{
    int warp = (blockIdx.x * blockDim.x + threadIdx.x) >> 5;
    int lane = threadIdx.x & 31;
    int bt = warp >> 1;
    int which = warp & 1;
    if (bt >= BT) return;
    const float* v = kqv + (size_t)bt * KQV_OUT + which * 768;
    float s = 0.f;
#pragma unroll 6
    for (int e = lane; e < 768; e += 32) { float x = v[e]; s = fmaf(x, x, s); }
#pragma unroll
    for (int o = 16; o; o >>= 1) s += __shfl_xor_sync(0xffffffffu, s, o);
    if (lane == 0) xd[(size_t)which * BT + bt] = 0.5f * s;
}

__global__ void ksum_partial(const float* __restrict__ kp, float* __restrict__ kpart)
{
    int b = blockIdx.x >> 5;
    int chunk = blockIdx.x & 31;
    int m = threadIdx.x;
    const float* base = kp + ((size_t)b * T + (size_t)chunk * 128) * MFEAT + m;
    float s = 0.f;
#pragma unroll 8
    for (int t = 0; t < 128; t++) s += base[(size_t)t * MFEAT];
    kpart[((size_t)b * 32 + chunk) * MFEAT + m] = s;
}

__global__ void ksum_reduce(const float* __restrict__ kpart, float* __restrict__ ksum)
{
    int idx = blockIdx.x * blockDim.x + threadIdx.x;
    if (idx >= BATCH * MFEAT) return;
    int b = idx / MFEAT, m = idx % MFEAT;
    float s = 0.f;
#pragma unroll
    for (int c = 0; c < 32; c++) s += kpart[((size_t)b * 32 + c) * MFEAT + m];
    ksum[idx] = s;
}

__global__ void dinv_kernel(const float* __restrict__ qp,
                            const float* __restrict__ ksum,
                            float* __restrict__ dinv)
{
    int warp = (blockIdx.x * blockDim.x + threadIdx.x) >> 5;
    int lane = threadIdx.x & 31;
    if (warp >= BT) return;
    int b = warp >> 12;
    const float* q  = qp + (size_t)warp * MFEAT;
    const float* ks = ksum + (size_t)b * MFEAT;
    float s = 0.f;
#pragma unroll 3
    for (int m = lane; m < MFEAT; m += 32) s = fmaf(q[m], ks[m], s);
#pragma unroll
    for (int o = 16; o; o >>= 1) s += __shfl_xor_sync(0xffffffffu, s, o);
    if (lane == 0) dinv[warp] = 1.0f / (s + EPS);
}

// ---------------- launch ----------------
extern "C" void kernel_launch(void* const* d_in, const int* in_sizes, int n_in,
                              void* d_out, int out_size)
{
    const float* x       = (const float*)d_in[0];
    const float* kqv_w1  = (const float*)d_in[1];
    const float* kqv_w2  = (const float*)d_in[2];
    const float* kqv_b   = (const float*)d_in[3];
    const float* proj_w1 = (const float*)d_in[4];
    const float* proj_w2 = (const float*)d_in[5];
    const float* proj_b  = (const float*)d_in[6];
    const float* w       = (const float*)d_in[7];
    float* out = (float*)d_out;

    float *o1, *kqv, *kpq, *xd, *kpart, *ksum, *kptvp, *kptv, *dinv, *y;
    cudaGetSymbolAddress((void**)&o1,   g_o1);
    cudaGetSymbolAddress((void**)&kqv,  g_kqv);
    cudaGetSymbolAddress((void**)&kpq,  g_kpq);
    cudaGetSymbolAddress((void**)&xd,   g_xd);
    cudaGetSymbolAddress((void**)&kpart,g_kpart);
    cudaGetSymbolAddress((void**)&ksum, g_ksum);
    cudaGetSymbolAddress((void**)&kptvp,g_kptvp);
    cudaGetSymbolAddress((void**)&kptv, g_kptv);
    cudaGetSymbolAddress((void**)&dinv, g_dinv);
    cudaGetSymbolAddress((void**)&y,    g_y);

    float* kp = kpq;
    float* qp = kpq + (size_t)BT * MFEAT;

    // 1) kqv monarch stage 1
    gemm_nt<<<dim3(192/TN, BT/TM, 4), 256>>>(
        x, DIM, 192, kqv_w1, 192*192, 192,
        o1, 768, 4, 1, 0,
        nullptr, nullptr, 0, MODE_NONE, 1.f);

    // 2) kqv monarch stage 2 (+bias)
    gemm_nt<<<dim3(576/TN, BT/TM, 4), 256>>>(
        o1, 768, 192, kqv_w2, 576*192, 192,
        kqv, KQV_OUT, 4, 1, 0,
        kqv_b, nullptr, 0, MODE_NONE, 1.f);

    // 3) 0.5*||k||^2, 0.5*||q||^2
    xd_kernel<<<(BT*2)/8, 256>>>(kqv, xd);

    // 4) kp/qp merged
    gemm_nt<<<dim3(MFEAT/TN, BT/TM, 2), 256>>>(
        kqv, KQV_OUT, 768, w, 0, 768,
        kpq, MFEAT, 1, 0, (long long)BT * MFEAT,
        nullptr, xd, BT, MODE_EXP, PRM_SCALE);

    // 5) ksum
    ksum_partial<<<BATCH*32, MFEAT>>>(kp, kpart);
    ksum_reduce<<<(BATCH*MFEAT + 255)/256, 256>>>(kpart, ksum);

    // 6) kptv split-K=4
    gemm_tn_kptv<<<dim3(MFEAT/TN, EMB/TM, BATCH*4), 256>>>(kqv + 1536, kp, kptvp);
    kptv_reduce<<<(BATCH*EMB*MFEAT + 255)/256, 256>>>(kptvp, kptv);

    // 7) dinv
    dinv_kernel<<<BT/8, 256>>>(qp, ksum, dinv);

    // 8) y = (qp @ kptv^T) * dinv
    gemm_nt<<<dim3(EMB/TN, T/TM, BATCH), 256>>>(
        qp, MFEAT, (long long)T * MFEAT,
        kptv, (long long)EMB * MFEAT, MFEAT,
        y, EMB, 1, 0, (long long)T * EMB,
        nullptr, dinv, T, MODE_RSC, 1.f);

    // 9) proj monarch stage 1
    gemm_nt<<<dim3(192/TN, BT/TM, 4), 256>>>(
        y, 768, 192, proj_w1, 192*192, 192,
        o1, 768, 4, 1, 0,
        nullptr, nullptr, 0, MODE_NONE, 1.f);

    // 10) proj monarch stage 2 -> output
    gemm_nt<<<dim3(192/TN, BT/TM, 4), 256>>>(
        o1, 768, 192, proj_w2, 192*192, 192,
        out, 768, 4, 1, 0,
        proj_b, nullptr, 0, MODE_NONE, 1.f);
}

// round 16
// speedup vs baseline: 1.6617x; 1.6617x over previous
#include <cuda_runtime.h>
#include <cuda_bf16.h>
#include <math.h>

// ---------------- problem constants ----------------
#define BATCH 8
#define T 4096
#define BT (BATCH*T)          // 32768
#define DIM 768
#define EMB 768
#define MFEAT 384
#define KQV_OUT 2304
#define PRM_SCALE 0.051031036307982884f   // 1/sqrt(384)
#define EPS 1e-8f

// ---------------- scratch (device globals) ----------------
__device__ float g_o1  [(size_t)BT*768];
__device__ float g_kqv [(size_t)BT*KQV_OUT];
__device__ float g_kpq [(size_t)2*BT*MFEAT];      // kp then qp
__device__ float g_xd  [2*BT];                    // xdk then xdq
__device__ float g_kpart[BATCH*32*MFEAT];
__device__ float g_ksum [BATCH*MFEAT];
__device__ float g_kptvp[(size_t)BATCH*4*EMB*MFEAT];
__device__ float g_kptv [(size_t)BATCH*EMB*MFEAT];
__device__ float g_dinv [BT];
__device__ float g_y   [(size_t)BT*768];

// ---------------- packed f32x2 FMA (Blackwell FFMA2) ----------------
typedef unsigned long long u64t;
#define FMA_X2(d, a, b) asm("fma.rn.f32x2 %0, %1, %2, %0;" : "+l"(d) : "l"(a), "l"(b))
// duplicate a scalar float into both halves of a 64-bit packed operand (register-side)
#define DUP2(d, s) asm("mov.b64 %0, {%1, %1};" : "=l"(d) : "r"(__float_as_uint(s)))
__device__ __forceinline__ float lo32(u64t v) { return __uint_as_float((unsigned)v); }
__device__ __forceinline__ float hi32(u64t v) { return __uint_as_float((unsigned)(v >> 32)); }

// ---------------- generic NT SGEMM: C = A (MxK, row-major) * B^T (B is NxK row-major)
// tile 256x64x16, 256 threads, 8x8 per thread; M packed in pairs for FFMA2.
#define TM 256
#define TN 64
#define TK 16

#define MODE_NONE 0
#define MODE_EXP  1   // v = exp(acc - rowv[row]) * scale
#define MODE_RSC  2   // v = acc * rowv[row]

__global__ __launch_bounds__(256, 2)
void gemm_nt(const float* __restrict__ A, int lda, long long aZoff,
             const float* __restrict__ Bm, long long bZoff, int K,
             float* __restrict__ C, int ldc, int cs, int czCo, long long cZoff,
             const float* __restrict__ bias,
             const float* __restrict__ rowv, int rvz,
             int mode, float scale)
{
    const int z = blockIdx.z;
    const float* Ab = A + (size_t)z * aZoff;
    const float* Bb = Bm + (size_t)z * bZoff;
    float*       Cb = C + (size_t)z * cZoff;

    const int rowBase = blockIdx.y * TM;
    const int colBase = blockIdx.x * TN;

    __shared__ __align__(16) float As[TK][TM + 4];   // stride 260 floats (16B mult)
    __shared__ __align__(16) float Bs[TK][TN + 4];   // stride 68 floats

    const int tid = threadIdx.x;
    const int tx = tid & 7;        // n-group: cols tx*4.. and tx*4+32..
    const int ty = tid >> 3;       // m-group: rows ty*8..ty*8+7

    const int ar  = tid >> 2;      // A stage: rows ar + i*64
    const int ac4 = tid & 3;       // A stage: f4 k-col
    const int br  = tid >> 2;      // B stage: n row (0..63)
    const int bc4 = tid & 3;       // B stage: f4 k-col

    float4 stA[4];
    float4 stB;

    u64t accP[4][8];               // [row-pair i2][col j]
#pragma unroll
    for (int i = 0; i < 4; i++)
#pragma unroll
        for (int j = 0; j < 8; j++) accP[i][j] = 0ull;

    const int nK = K / TK;

    // prologue loads
#pragma unroll
    for (int i = 0; i < 4; i++) {
        int r = ar + i * 64;
        stA[i] = *reinterpret_cast<const float4*>(&Ab[(size_t)(rowBase + r) * lda + ac4 * 4]);
    }
    stB = *reinterpret_cast<const float4*>(&Bb[(size_t)(colBase + br) * K + bc4 * 4]);

    int k0 = 0;
    for (int kb = 0; kb < nK; ++kb) {
        // stage A (transposed scatter)
#pragma unroll
        for (int i = 0; i < 4; i++) {
            int r = ar + i * 64;
            As[ac4 * 4 + 0][r] = stA[i].x;
            As[ac4 * 4 + 1][r] = stA[i].y;
            As[ac4 * 4 + 2][r] = stA[i].z;
            As[ac4 * 4 + 3][r] = stA[i].w;
        }
        Bs[bc4 * 4 + 0][br] = stB.x;
        Bs[bc4 * 4 + 1][br] = stB.y;
        Bs[bc4 * 4 + 2][br] = stB.z;
        Bs[bc4 * 4 + 3][br] = stB.w;
        __syncthreads();

        if (kb + 1 < nK) {
            k0 += TK;
#pragma unroll
            for (int i = 0; i < 4; i++) {
                int r = ar + i * 64;
                stA[i] = *reinterpret_cast<const float4*>(&Ab[(size_t)(rowBase + r) * lda + k0 + ac4 * 4]);
            }
            stB = *reinterpret_cast<const float4*>(&Bb[(size_t)(colBase + br) * K + k0 + bc4 * 4]);
        }

#pragma unroll
        for (int kk = 0; kk < TK; ++kk) {
            ulonglong2 a01 = *reinterpret_cast<const ulonglong2*>(&As[kk][ty * 8]);
            ulonglong2 a23 = *reinterpret_cast<const ulonglong2*>(&As[kk][ty * 8 + 4]);
            float4 b0 = *reinterpret_cast<const float4*>(&Bs[kk][tx * 4]);
            float4 b1 = *reinterpret_cast<const float4*>(&Bs[kk][tx * 4 + 32]);
            u64t pa[4] = {a01.x, a01.y, a23.x, a23.y};
            u64t bd[8];
            DUP2(bd[0], b0.x); DUP2(bd[1], b0.y); DUP2(bd[2], b0.z); DUP2(bd[3], b0.w);
            DUP2(bd[4], b1.x); DUP2(bd[5], b1.y); DUP2(bd[6], b1.z); DUP2(bd[7], b1.w);
#pragma unroll
            for (int i2 = 0; i2 < 4; i2++)
#pragma unroll
                for (int j = 0; j < 8; j++)
                    FMA_X2(accP[i2][j], pa[i2], bd[j]);
        }
        __syncthreads();
    }

    // unpack pairs -> c[8][8]
    float c[8][8];
#pragma unroll
    for (int i2 = 0; i2 < 4; i2++)
#pragma unroll
        for (int j = 0; j < 8; j++) {
            c[2 * i2 + 0][j] = lo32(accP[i2][j]);
            c[2 * i2 + 1][j] = hi32(accP[i2][j]);
        }

    const int row0 = rowBase + ty * 8;
    const int c0 = colBase + tx * 4;
    const int c1 = c0 + 32;

    if (cs == 1) {
#pragma unroll
        for (int i = 0; i < 8; i++) {
            float rv = 0.f;
            if (mode != MODE_NONE) rv = rowv[(size_t)z * rvz + row0 + i];
            float4 v0, v1;
            if (mode == MODE_EXP) {
                v0.x = expf(c[i][0] - rv) * scale; v0.y = expf(c[i][1] - rv) * scale;
                v0.z = expf(c[i][2] - rv) * scale; v0.w = expf(c[i][3] - rv) * scale;
                v1.x = expf(c[i][4] - rv) * scale; v1.y = expf(c[i][5] - rv) * scale;
                v1.z = expf(c[i][6] - rv) * scale; v1.w = expf(c[i][7] - rv) * scale;
            } else if (mode == MODE_RSC) {
                v0.x = c[i][0] * rv; v0.y = c[i][1] * rv; v0.z = c[i][2] * rv; v0.w = c[i][3] * rv;
                v1.x = c[i][4] * rv; v1.y = c[i][5] * rv; v1.z = c[i][6] * rv; v1.w = c[i][7] * rv;
            } else {
                v0 = make_float4(c[i][0], c[i][1], c[i][2], c[i][3]);
                v1 = make_float4(c[i][4], c[i][5], c[i][6], c[i][7]);
            }
            size_t rb = (size_t)(row0 + i) * ldc;
            *reinterpret_cast<float4*>(&Cb[rb + c0]) = v0;
            *reinterpret_cast<float4*>(&Cb[rb + c1]) = v1;
        }
    } else {
        // scattered monarch-permutation store: colMem = col*cs + z*czCo
#pragma unroll
        for (int i = 0; i < 8; i++) {
            size_t rb = (size_t)(row0 + i) * ldc;
#pragma unroll
            for (int j = 0; j < 4; j++) {
                int cm = (c0 + j) * cs + z * czCo;
                float v = c[i][j];
                if (bias) v += bias[cm];
                Cb[rb + cm] = v;
            }
#pragma unroll
            for (int j = 0; j < 4; j++) {
                int cm = (c1 + j) * cs + z * czCo;
                float v = c[i][4 + j];
                if (bias) v += bias[cm];
                Cb[rb + cm] = v;
            }
        }
    }
}

// ---------------- TN SGEMM for kptv (split-K=4): part[z][n,m] = sum_t v[t,n]*kp[t,m]
__global__ __launch_bounds__(256, 2)
void gemm_tn_kptv(const float* __restrict__ Vg,   // kqv + 1536
                  const float* __restrict__ KPg,  // kp
                  float* __restrict__ part)
{
    const int z = blockIdx.z;
    const int b = z >> 2, s = z & 3;
    const float* Ab = Vg  + ((size_t)b * T + (size_t)s * 1024) * KQV_OUT;
    const float* Bb = KPg + ((size_t)b * T + (size_t)s * 1024) * MFEAT;
    float*       Cb = part + (size_t)z * EMB * MFEAT;

    const int nBase = blockIdx.y * TM;
    const int mBase = blockIdx.x * TN;

    __shared__ __align__(16) float As[TK][TM + 4];
    __shared__ __align__(16) float Bs[TK][TN + 4];

    const int tid = threadIdx.x;
    const int tx = tid & 7;
    const int ty = tid >> 3;

    const int a_tk0 = tid >> 6;
    const int a_n4  = tid & 63;
    const int b_tk  = tid >> 4;
    const int b_m4  = tid & 15;

    float4 stA[4];
    float4 stB;

    u64t accP[4][8];
#pragma unroll
    for (int i = 0; i < 4; i++)
#pragma unroll
        for (int j = 0; j < 8; j++) accP[i][j] = 0ull;

    const int nK = 1024 / TK;

#pragma unroll
    for (int i = 0; i < 4; i++) {
        int tk = a_tk0 + i * 4;
        stA[i] = *reinterpret_cast<const float4*>(&Ab[(size_t)tk * KQV_OUT + nBase + a_n4 * 4]);
    }
    stB = *reinterpret_cast<const float4*>(&Bb[(size_t)b_tk * MFEAT + mBase + b_m4 * 4]);

    int k0 = 0;
    for (int kb = 0; kb < nK; ++kb) {
#pragma unroll
        for (int i = 0; i < 4; i++) {
            int tk = a_tk0 + i * 4;
            *reinterpret_cast<float4*>(&As[tk][a_n4 * 4]) = stA[i];
        }
        *reinterpret_cast<float4*>(&Bs[b_tk][b_m4 * 4]) = stB;
        __syncthreads();

        if (kb + 1 < nK) {
            k0 += TK;
#pragma unroll
            for (int i = 0; i < 4; i++) {
                int tk = k0 + a_tk0 + i * 4;
                stA[i] = *reinterpret_cast<const float4*>(&Ab[(size_t)tk * KQV_OUT + nBase + a_n4 * 4]);
            }
            stB = *reinterpret_cast<const float4*>(&Bb[(size_t)(k0 + b_tk) * MFEAT + mBase + b_m4 * 4]);
        }

#pragma unroll
        for (int kk = 0; kk < TK; ++kk) {
            ulonglong2 a01 = *reinterpret_cast<const ulonglong2*>(&As[kk][ty * 8]);
            ulonglong2 a23 = *reinterpret_cast<const ulonglong2*>(&As[kk][ty * 8 + 4]);
            float4 b0 = *reinterpret_cast<const float4*>(&Bs[kk][tx * 4]);
            float4 b1 = *reinterpret_cast<const float4*>(&Bs[kk][tx * 4 + 32]);
            u64t pa[4] = {a01.x, a01.y, a23.x, a23.y};
            u64t bd[8];
            DUP2(bd[0], b0.x); DUP2(bd[1], b0.y); DUP2(bd[2], b0.z); DUP2(bd[3], b0.w);
            DUP2(bd[4], b1.x); DUP2(bd[5], b1.y); DUP2(bd[6], b1.z); DUP2(bd[7], b1.w);
#pragma unroll
            for (int i2 = 0; i2 < 4; i2++)
#pragma unroll
                for (int j = 0; j < 8; j++)
                    FMA_X2(accP[i2][j], pa[i2], bd[j]);
        }
        __syncthreads();
    }

    const int row0 = nBase + ty * 8;
    const int c0 = mBase + tx * 4;
#pragma unroll
    for (int i2 = 0; i2 < 4; i2++)
#pragma unroll
        for (int h = 0; h < 2; h++) {
            int i = 2 * i2 + h;
            float4 v0, v1;
            if (h == 0) {
                v0 = make_float4(lo32(accP[i2][0]), lo32(accP[i2][1]), lo32(accP[i2][2]), lo32(accP[i2][3]));
                v1 = make_float4(lo32(accP[i2][4]), lo32(accP[i2][5]), lo32(accP[i2][6]), lo32(accP[i2][7]));
            } else {
                v0 = make_float4(hi32(accP[i2][0]), hi32(accP[i2][1]), hi32(accP[i2][2]), hi32(accP[i2][3]));
                v1 = make_float4(hi32(accP[i2][4]), hi32(accP[i2][5]), hi32(accP[i2][6]), hi32(accP[i2][7]));
            }
            size_t rb = (size_t)(row0 + i) * MFEAT;
            *reinterpret_cast<float4*>(&Cb[rb + c0])      = v0;
            *reinterpret_cast<float4*>(&Cb[rb + c0 + 32]) = v1;
        }
}

__global__ void kptv_reduce(const float* __restrict__ part, float* __restrict__ kptv)
{
    size_t i = (size_t)blockIdx.x * blockDim.x + threadIdx.x;
    const size_t N = (size_t)BATCH * EMB * MFEAT;
    if (i >= N) return;
    int b = (int)(i / (EMB * MFEAT));
    size_t off = i - (size_t)b * EMB * MFEAT;
    const float* p = part + (size_t)b * 4 * EMB * MFEAT + off;
    kptv[i] = p[0] + p[(size_t)EMB * MFEAT] + p[(size_t)2 * EMB * MFEAT] + p[(size_t)3 * EMB * MFEAT];
}

// ---------------- helper kernels ----------------
__global__ void xd_kernel(const float* __restrict__ kqv, float* __restrict__ xd)
{
    int warp = (blockIdx.x * blockDim.x + threadIdx.x) >> 5;
    int lane = threadIdx.x & 31;
    int bt = warp >> 1;
    int which = warp & 1;
    if (bt >= BT) return;
    const float* v = kqv + (size_t)bt * KQV_OUT + which * 768;
    float s = 0.f;
#pragma unroll 6
    for (int e = lane; e < 768; e += 32) { float x = v[e]; s = fmaf(x, x, s); }
#pragma unroll
    for (int o = 16; o; o >>= 1) s += __shfl_xor_sync(0xffffffffu, s, o);
    if (lane == 0) xd[(size_t)which * BT + bt] = 0.5f * s;
}

__global__ void ksum_partial(const float* __restrict__ kp, float* __restrict__ kpart)
{
    int b = blockIdx.x >> 5;
    int chunk = blockIdx.x & 31;
    int m = threadIdx.x;
    const float* base = kp + ((size_t)b * T + (size_t)chunk * 128) * MFEAT + m;
    float s = 0.f;
#pragma unroll 8
    for (int t = 0; t < 128; t++) s += base[(size_t)t * MFEAT];
    kpart[((size_t)b * 32 + chunk) * MFEAT + m] = s;
}

__global__ void ksum_reduce(const float* __restrict__ kpart, float* __restrict__ ksum)
{
    int idx = blockIdx.x * blockDim.x + threadIdx.x;
    if (idx >= BATCH * MFEAT) return;
    int b = idx / MFEAT, m = idx % MFEAT;
    float s = 0.f;
#pragma unroll
    for (int c = 0; c < 32; c++) s += kpart[((size_t)b * 32 + c) * MFEAT + m];
    ksum[idx] = s;
}

__global__ void dinv_kernel(const float* __restrict__ qp,
                            const float* __restrict__ ksum,
                            float* __restrict__ dinv)
{
    int warp = (blockIdx.x * blockDim.x + threadIdx.x) >> 5;
    int lane = threadIdx.x & 31;
    if (warp >= BT) return;
    int b = warp >> 12;
    const float* q  = qp + (size_t)warp * MFEAT;
    const float* ks = ksum + (size_t)b * MFEAT;
    float s = 0.f;
#pragma unroll 3
    for (int m = lane; m < MFEAT; m += 32) s = fmaf(q[m], ks[m], s);
#pragma unroll
    for (int o = 16; o; o >>= 1) s += __shfl_xor_sync(0xffffffffu, s, o);
    if (lane == 0) dinv[warp] = 1.0f / (s + EPS);
}

// ---------------- launch ----------------
extern "C" void kernel_launch(void* const* d_in, const int* in_sizes, int n_in,
                              void* d_out, int out_size)
{
    const float* x       = (const float*)d_in[0];
    const float* kqv_w1  = (const float*)d_in[1];
    const float* kqv_w2  = (const float*)d_in[2];
    const float* kqv_b   = (const float*)d_in[3];
    const float* proj_w1 = (const float*)d_in[4];
    const float* proj_w2 = (const float*)d_in[5];
    const float* proj_b  = (const float*)d_in[6];
    const float* w       = (const float*)d_in[7];
    float* out = (float*)d_out;

    float *o1, *kqv, *kpq, *xd, *kpart, *ksum, *kptvp, *kptv, *dinv, *y;
    cudaGetSymbolAddress((void**)&o1,   g_o1);
    cudaGetSymbolAddress((void**)&kqv,  g_kqv);
    cudaGetSymbolAddress((void**)&kpq,  g_kpq);
    cudaGetSymbolAddress((void**)&xd,   g_xd);
    cudaGetSymbolAddress((void**)&kpart,g_kpart);
    cudaGetSymbolAddress((void**)&ksum, g_ksum);
    cudaGetSymbolAddress((void**)&kptvp,g_kptvp);
    cudaGetSymbolAddress((void**)&kptv, g_kptv);
    cudaGetSymbolAddress((void**)&dinv, g_dinv);
    cudaGetSymbolAddress((void**)&y,    g_y);

    float* kp = kpq;
    float* qp = kpq + (size_t)BT * MFEAT;

    // 1) kqv monarch stage 1
    gemm_nt<<<dim3(192/TN, BT/TM, 4), 256>>>(
        x, DIM, 192, kqv_w1, 192*192, 192,
        o1, 768, 4, 1, 0,
        nullptr, nullptr, 0, MODE_NONE, 1.f);

    // 2) kqv monarch stage 2 (+bias)
    gemm_nt<<<dim3(576/TN, BT/TM, 4), 256>>>(
        o1, 768, 192, kqv_w2, 576*192, 192,
        kqv, KQV_OUT, 4, 1, 0,
        kqv_b, nullptr, 0, MODE_NONE, 1.f);

    // 3) 0.5*||k||^2, 0.5*||q||^2
    xd_kernel<<<(BT*2)/8, 256>>>(kqv, xd);

    // 4) kp/qp merged
    gemm_nt<<<dim3(MFEAT/TN, BT/TM, 2), 256>>>(
        kqv, KQV_OUT, 768, w, 0, 768,
        kpq, MFEAT, 1, 0, (long long)BT * MFEAT,
        nullptr, xd, BT, MODE_EXP, PRM_SCALE);

    // 5) ksum
    ksum_partial<<<BATCH*32, MFEAT>>>(kp, kpart);
    ksum_reduce<<<(BATCH*MFEAT + 255)/256, 256>>>(kpart, ksum);

    // 6) kptv split-K=4
    gemm_tn_kptv<<<dim3(MFEAT/TN, EMB/TM, BATCH*4), 256>>>(kqv + 1536, kp, kptvp);
    kptv_reduce<<<(BATCH*EMB*MFEAT + 255)/256, 256>>>(kptvp, kptv);

    // 7) dinv
    dinv_kernel<<<BT/8, 256>>>(qp, ksum, dinv);

    // 8) y = (qp @ kptv^T) * dinv
    gemm_nt<<<dim3(EMB/TN, T/TM, BATCH), 256>>>(
        qp, MFEAT, (long long)T * MFEAT,
        kptv, (long long)EMB * MFEAT, MFEAT,
        y, EMB, 1, 0, (long long)T * EMB,
        nullptr, dinv, T, MODE_RSC, 1.f);

    // 9) proj monarch stage 1
    gemm_nt<<<dim3(192/TN, BT/TM, 4), 256>>>(
        y, 768, 192, proj_w1, 192*192, 192,
        o1, 768, 4, 1, 0,
        nullptr, nullptr, 0, MODE_NONE, 1.f);

    // 10) proj monarch stage 2 -> output
    gemm_nt<<<dim3(192/TN, BT/TM, 4), 256>>>(
        o1, 768, 192, proj_w2, 192*192, 192,
        out, 768, 4, 1, 0,
        proj_b, nullptr, 0, MODE_NONE, 1.f);
}

// round 17
// speedup vs baseline: 1.6730x; 1.0068x over previous
#include <cuda_runtime.h>
#include <cuda_bf16.h>
#include <math.h>

// ---------------- problem constants ----------------
#define BATCH 8
#define T 4096
#define BT (BATCH*T)          // 32768
#define DIM 768
#define EMB 768
#define MFEAT 384
#define KQV_OUT 2304
#define PRM_SCALE 0.051031036307982884f   // 1/sqrt(384)
#define EPS 1e-8f

// ---------------- scratch (device globals) ----------------
__device__ float g_o1  [(size_t)BT*768];
__device__ float g_kqv [(size_t)BT*KQV_OUT];
__device__ float g_kpq [(size_t)2*BT*MFEAT];      // kp then qp
__device__ float g_xd  [2*BT];                    // xdk then xdq
__device__ float g_kpart[BATCH*32*MFEAT];
__device__ float g_ksum [BATCH*MFEAT];
__device__ float g_kptvp[(size_t)BATCH*4*EMB*MFEAT];
__device__ float g_kptv [(size_t)BATCH*EMB*MFEAT];
__device__ float g_dinv [BT];
__device__ float g_y   [(size_t)BT*768];

// ---------------- packed f32x2 FMA (Blackwell FFMA2) ----------------
typedef unsigned long long u64t;
#define FMA_X2(d, a, b) asm("fma.rn.f32x2 %0, %1, %2, %0;" : "+l"(d) : "l"(a), "l"(b))
// duplicate a scalar float into both halves of a 64-bit packed operand (register-side)
#define DUP2(d, s) asm("mov.b64 %0, {%1, %1};" : "=l"(d) : "r"(__float_as_uint(s)))
__device__ __forceinline__ float lo32(u64t v) { return __uint_as_float((unsigned)v); }
__device__ __forceinline__ float hi32(u64t v) { return __uint_as_float((unsigned)(v >> 32)); }

// ---------------- generic NT SGEMM: C = A (MxK, row-major) * B^T (B is NxK row-major)
// tile 256x64x16, 256 threads, 8x8 per thread; M packed in pairs for FFMA2.
#define TM 256
#define TN 64
#define TK 16

#define MODE_NONE 0
#define MODE_EXP  1   // v = exp(acc - rowv[row]) * scale
#define MODE_RSC  2   // v = acc * rowv[row]

__global__ __launch_bounds__(256, 2)
void gemm_nt(const float* __restrict__ A, int lda, long long aZoff,
             const float* __restrict__ Bm, long long bZoff, int K,
             float* __restrict__ C, int ldc, int cs, int czCo, long long cZoff,
             const float* __restrict__ bias,
             const float* __restrict__ rowv, int rvz,
             int mode, float scale)
{
    const int z = blockIdx.z;
    const float* Ab = A + (size_t)z * aZoff;
    const float* Bb = Bm + (size_t)z * bZoff;
    float*       Cb = C + (size_t)z * cZoff;

    const int rowBase = blockIdx.y * TM;
    const int colBase = blockIdx.x * TN;

    __shared__ __align__(16) float As[TK][TM + 4];   // stride 260 floats (16B mult)
    __shared__ __align__(16) float Bs[TK][TN + 4];   // stride 68 floats

    const int tid = threadIdx.x;
    const int tx = tid & 7;        // n-group: cols tx*4.. and tx*4+32..
    const int ty = tid >> 3;       // m-group: rows ty*8..ty*8+7

    const int ar  = tid >> 2;      // A stage: rows ar + i*64
    const int ac4 = tid & 3;       // A stage: f4 k-col
    const int br  = tid >> 2;      // B stage: n row (0..63)
    const int bc4 = tid & 3;       // B stage: f4 k-col

    float4 stA[4];
    float4 stB;

    u64t accP[4][8];               // [row-pair i2][col j]
#pragma unroll
    for (int i = 0; i < 4; i++)
#pragma unroll
        for (int j = 0; j < 8; j++) accP[i][j] = 0ull;

    const int nK = K / TK;

    // prologue loads
#pragma unroll
    for (int i = 0; i < 4; i++) {
        int r = ar + i * 64;
        stA[i] = *reinterpret_cast<const float4*>(&Ab[(size_t)(rowBase + r) * lda + ac4 * 4]);
    }
    stB = *reinterpret_cast<const float4*>(&Bb[(size_t)(colBase + br) * K + bc4 * 4]);

    int k0 = 0;
    for (int kb = 0; kb < nK; ++kb) {
        // stage A (transposed scatter)
#pragma unroll
        for (int i = 0; i < 4; i++) {
            int r = ar + i * 64;
            As[ac4 * 4 + 0][r] = stA[i].x;
            As[ac4 * 4 + 1][r] = stA[i].y;
            As[ac4 * 4 + 2][r] = stA[i].z;
            As[ac4 * 4 + 3][r] = stA[i].w;
        }
        Bs[bc4 * 4 + 0][br] = stB.x;
        Bs[bc4 * 4 + 1][br] = stB.y;
        Bs[bc4 * 4 + 2][br] = stB.z;
        Bs[bc4 * 4 + 3][br] = stB.w;
        __syncthreads();

        if (kb + 1 < nK) {
            k0 += TK;
#pragma unroll
            for (int i = 0; i < 4; i++) {
                int r = ar + i * 64;
                stA[i] = *reinterpret_cast<const float4*>(&Ab[(size_t)(rowBase + r) * lda + k0 + ac4 * 4]);
            }
            stB = *reinterpret_cast<const float4*>(&Bb[(size_t)(colBase + br) * K + k0 + bc4 * 4]);
        }

#pragma unroll
        for (int kk = 0; kk < TK; ++kk) {
            ulonglong2 a01 = *reinterpret_cast<const ulonglong2*>(&As[kk][ty * 8]);
            ulonglong2 a23 = *reinterpret_cast<const ulonglong2*>(&As[kk][ty * 8 + 4]);
            float4 b0 = *reinterpret_cast<const float4*>(&Bs[kk][tx * 4]);
            float4 b1 = *reinterpret_cast<const float4*>(&Bs[kk][tx * 4 + 32]);
            u64t pa[4] = {a01.x, a01.y, a23.x, a23.y};
            u64t bd[8];
            DUP2(bd[0], b0.x); DUP2(bd[1], b0.y); DUP2(bd[2], b0.z); DUP2(bd[3], b0.w);
            DUP2(bd[4], b1.x); DUP2(bd[5], b1.y); DUP2(bd[6], b1.z); DUP2(bd[7], b1.w);
#pragma unroll
            for (int i2 = 0; i2 < 4; i2++)
#pragma unroll
                for (int j = 0; j < 8; j++)
                    FMA_X2(accP[i2][j], pa[i2], bd[j]);
        }
        __syncthreads();
    }

    // unpack pairs -> c[8][8]
    float c[8][8];
#pragma unroll
    for (int i2 = 0; i2 < 4; i2++)
#pragma unroll
        for (int j = 0; j < 8; j++) {
            c[2 * i2 + 0][j] = lo32(accP[i2][j]);
            c[2 * i2 + 1][j] = hi32(accP[i2][j]);
        }

    const int row0 = rowBase + ty * 8;
    const int c0 = colBase + tx * 4;
    const int c1 = c0 + 32;

    if (cs == 1) {
#pragma unroll
        for (int i = 0; i < 8; i++) {
            float rv = 0.f;
            if (mode != MODE_NONE) rv = rowv[(size_t)z * rvz + row0 + i];
            float4 v0, v1;
            if (mode == MODE_EXP) {
                v0.x = expf(c[i][0] - rv) * scale; v0.y = expf(c[i][1] - rv) * scale;
                v0.z = expf(c[i][2] - rv) * scale; v0.w = expf(c[i][3] - rv) * scale;
                v1.x = expf(c[i][4] - rv) * scale; v1.y = expf(c[i][5] - rv) * scale;
                v1.z = expf(c[i][6] - rv) * scale; v1.w = expf(c[i][7] - rv) * scale;
            } else if (mode == MODE_RSC) {
                v0.x = c[i][0] * rv; v0.y = c[i][1] * rv; v0.z = c[i][2] * rv; v0.w = c[i][3] * rv;
                v1.x = c[i][4] * rv; v1.y = c[i][5] * rv; v1.z = c[i][6] * rv; v1.w = c[i][7] * rv;
            } else {
                v0 = make_float4(c[i][0], c[i][1], c[i][2], c[i][3]);
                v1 = make_float4(c[i][4], c[i][5], c[i][6], c[i][7]);
            }
            size_t rb = (size_t)(row0 + i) * ldc;
            *reinterpret_cast<float4*>(&Cb[rb + c0]) = v0;
            *reinterpret_cast<float4*>(&Cb[rb + c1]) = v1;
        }
    } else {
        // scattered monarch-permutation store: colMem = col*cs + z*czCo
#pragma unroll
        for (int i = 0; i < 8; i++) {
            size_t rb = (size_t)(row0 + i) * ldc;
#pragma unroll
            for (int j = 0; j < 4; j++) {
                int cm = (c0 + j) * cs + z * czCo;
                float v = c[i][j];
                if (bias) v += bias[cm];
                Cb[rb + cm] = v;
            }
#pragma unroll
            for (int j = 0; j < 4; j++) {
                int cm = (c1 + j) * cs + z * czCo;
                float v = c[i][4 + j];
                if (bias) v += bias[cm];
                Cb[rb + cm] = v;
            }
        }
    }
}

// ---------------- TN SGEMM for kptv (split-K=4): part[z][n,m] = sum_t v[t,n]*kp[t,m]
__global__ __launch_bounds__(256, 2)
void gemm_tn_kptv(const float* __restrict__ Vg,   // kqv + 1536
                  const float* __restrict__ KPg,  // kp
                  float* __restrict__ part)
{
    const int z = blockIdx.z;
    const int b = z >> 2, s = z & 3;
    const float* Ab = Vg  + ((size_t)b * T + (size_t)s * 1024) * KQV_OUT;
    const float* Bb = KPg + ((size_t)b * T + (size_t)s * 1024) * MFEAT;
    float*       Cb = part + (size_t)z * EMB * MFEAT;

    const int nBase = blockIdx.y * TM;
    const int mBase = blockIdx.x * TN;

    __shared__ __align__(16) float As[TK][TM + 4];
    __shared__ __align__(16) float Bs[TK][TN + 4];

    const int tid = threadIdx.x;
    const int tx = tid & 7;
    const int ty = tid >> 3;

    const int a_tk0 = tid >> 6;
    const int a_n4  = tid & 63;
    const int b_tk  = tid >> 4;
    const int b_m4  = tid & 15;

    float4 stA[4];
    float4 stB;

    u64t accP[4][8];
#pragma unroll
    for (int i = 0; i < 4; i++)
#pragma unroll
        for (int j = 0; j < 8; j++) accP[i][j] = 0ull;

    const int nK = 1024 / TK;

#pragma unroll
    for (int i = 0; i < 4; i++) {
        int tk = a_tk0 + i * 4;
        stA[i] = *reinterpret_cast<const float4*>(&Ab[(size_t)tk * KQV_OUT + nBase + a_n4 * 4]);
    }
    stB = *reinterpret_cast<const float4*>(&Bb[(size_t)b_tk * MFEAT + mBase + b_m4 * 4]);

    int k0 = 0;
    for (int kb = 0; kb < nK; ++kb) {
#pragma unroll
        for (int i = 0; i < 4; i++) {
            int tk = a_tk0 + i * 4;
            *reinterpret_cast<float4*>(&As[tk][a_n4 * 4]) = stA[i];
        }
        *reinterpret_cast<float4*>(&Bs[b_tk][b_m4 * 4]) = stB;
        __syncthreads();

        if (kb + 1 < nK) {
            k0 += TK;
#pragma unroll
            for (int i = 0; i < 4; i++) {
                int tk = k0 + a_tk0 + i * 4;
                stA[i] = *reinterpret_cast<const float4*>(&Ab[(size_t)tk * KQV_OUT + nBase + a_n4 * 4]);
            }
            stB = *reinterpret_cast<const float4*>(&Bb[(size_t)(k0 + b_tk) * MFEAT + mBase + b_m4 * 4]);
        }

#pragma unroll
        for (int kk = 0; kk < TK; ++kk) {
            ulonglong2 a01 = *reinterpret_cast<const ulonglong2*>(&As[kk][ty * 8]);
            ulonglong2 a23 = *reinterpret_cast<const ulonglong2*>(&As[kk][ty * 8 + 4]);
            float4 b0 = *reinterpret_cast<const float4*>(&Bs[kk][tx * 4]);
            float4 b1 = *reinterpret_cast<const float4*>(&Bs[kk][tx * 4 + 32]);
            u64t pa[4] = {a01.x, a01.y, a23.x, a23.y};
            u64t bd[8];
            DUP2(bd[0], b0.x); DUP2(bd[1], b0.y); DUP2(bd[2], b0.z); DUP2(bd[3], b0.w);
            DUP2(bd[4], b1.x); DUP2(bd[5], b1.y); DUP2(bd[6], b1.z); DUP2(bd[7], b1.w);
#pragma unroll
            for (int i2 = 0; i2 < 4; i2++)
#pragma unroll
                for (int j = 0; j < 8; j++)
                    FMA_X2(accP[i2][j], pa[i2], bd[j]);
        }
        __syncthreads();
    }

    const int row0 = nBase + ty * 8;
    const int c0 = mBase + tx * 4;
#pragma unroll
    for (int i2 = 0; i2 < 4; i2++)
#pragma unroll
        for (int h = 0; h < 2; h++) {
            int i = 2 * i2 + h;
            float4 v0, v1;
            if (h == 0) {
                v0 = make_float4(lo32(accP[i2][0]), lo32(accP[i2][1]), lo32(accP[i2][2]), lo32(accP[i2][3]));
                v1 = make_float4(lo32(accP[i2][4]), lo32(accP[i2][5]), lo32(accP[i2][6]), lo32(accP[i2][7]));
            } else {
                v0 = make_float4(hi32(accP[i2][0]), hi32(accP[i2][1]), hi32(accP[i2][2]), hi32(accP[i2][3]));
                v1 = make_float4(hi32(accP[i2][4]), hi32(accP[i2][5]), hi32(accP[i2][6]), hi32(accP[i2][7]));
            }
            size_t rb = (size_t)(row0 + i) * MFEAT;
            *reinterpret_cast<float4*>(&Cb[rb + c0])      = v0;
            *reinterpret_cast<float4*>(&Cb[rb + c0 + 32]) = v1;
        }
}

__global__ void kptv_reduce(const float* __restrict__ part, float* __restrict__ kptv)
{
    size_t i = (size_t)blockIdx.x * blockDim.x + threadIdx.x;
    const size_t N = (size_t)BATCH * EMB * MFEAT;
    if (i >= N) return;
    int b = (int)(i / (EMB * MFEAT));
    size_t off = i - (size_t)b * EMB * MFEAT;
    const float* p = part + (size_t)b * 4 * EMB * MFEAT + off;
    kptv[i] = p[0] + p[(size_t)EMB * MFEAT] + p[(size_t)2 * EMB * MFEAT] + p[(size_t)3 * EMB * MFEAT];
}

// ---------------- helper kernels ----------------
__global__ void xd_kernel(const float* __restrict__ kqv, float* __restrict__ xd)
{
    int warp = (blockIdx.x * blockDim.x + threadIdx.x) >> 5;
    int lane = threadIdx.x & 31;
    int bt = warp >> 1;
    int which = warp & 1;
    if (bt >= BT) return;
    const float* v = kqv + (size_t)bt * KQV_OUT + which * 768;
    float s = 0.f;
#pragma unroll 6
    for (int e = lane; e < 768; e += 32) { float x = v[e]; s = fmaf(x, x, s); }
#pragma unroll
    for (int o = 16; o; o >>= 1) s += __shfl_xor_sync(0xffffffffu, s, o);
    if (lane == 0) xd[(size_t)which * BT + bt] = 0.5f * s;
}

__global__ void ksum_partial(const float* __restrict__ kp, float* __restrict__ kpart)
{
    int b = blockIdx.x >> 5;
    int chunk = blockIdx.x & 31;
    int m = threadIdx.x;
    const float* base = kp + ((size_t)b * T + (size_t)chunk * 128) * MFEAT + m;
    float s = 0.f;
#pragma unroll 8
    for (int t = 0; t < 128; t++) s += base[(size_t)t * MFEAT];
    kpart[((size_t)b * 32 + chunk) * MFEAT + m] = s;
}

__global__ void ksum_reduce(const float* __restrict__ kpart, float* __restrict__ ksum)
{
    int idx = blockIdx.x * blockDim.x + threadIdx.x;
    if (idx >= BATCH * MFEAT) return;
    int b = idx / MFEAT, m = idx % MFEAT;
    float s = 0.f;
#pragma unroll
    for (int c = 0; c < 32; c++) s += kpart[((size_t)b * 32 + c) * MFEAT + m];
    ksum[idx] = s;
}

__global__ void dinv_kernel(const float* __restrict__ qp,
                            const float* __restrict__ ksum,
                            float* __restrict__ dinv)
{
    int warp = (blockIdx.x * blockDim.x + threadIdx.x) >> 5;
    int lane = threadIdx.x & 31;
    if (warp >= BT) return;
    int b = warp >> 12;
    const float* q  = qp + (size_t)warp * MFEAT;
    const float* ks = ksum + (size_t)b * MFEAT;
    float s = 0.f;
#pragma unroll 3
    for (int m = lane; m < MFEAT; m += 32) s = fmaf(q[m], ks[m], s);
#pragma unroll
    for (int o = 16; o; o >>= 1) s += __shfl_xor_sync(0xffffffffu, s, o);
    if (lane == 0) dinv[warp] = 1.0f / (s + EPS);
}

// ---------------- launch ----------------
extern "C" void kernel_launch(void* const* d_in, const int* in_sizes, int n_in,
                              void* d_out, int out_size)
{
    const float* x       = (const float*)d_in[0];
    const float* kqv_w1  = (const float*)d_in[1];
    const float* kqv_w2  = (const float*)d_in[2];
    const float* kqv_b   = (const float*)d_in[3];
    const float* proj_w1 = (const float*)d_in[4];
    const float* proj_w2 = (const float*)d_in[5];
    const float* proj_b  = (const float*)d_in[6];
    const float* w       = (const float*)d_in[7];
    float* out = (float*)d_out;

    float *o1, *kqv, *kpq, *xd, *kpart, *ksum, *kptvp, *kptv, *dinv, *y;
    cudaGetSymbolAddress((void**)&o1,   g_o1);
    cudaGetSymbolAddress((void**)&kqv,  g_kqv);
    cudaGetSymbolAddress((void**)&kpq,  g_kpq);
    cudaGetSymbolAddress((void**)&xd,   g_xd);
    cudaGetSymbolAddress((void**)&kpart,g_kpart);
    cudaGetSymbolAddress((void**)&ksum, g_ksum);
    cudaGetSymbolAddress((void**)&kptvp,g_kptvp);
    cudaGetSymbolAddress((void**)&kptv, g_kptv);
    cudaGetSymbolAddress((void**)&dinv, g_dinv);
    cudaGetSymbolAddress((void**)&y,    g_y);

    float* kp = kpq;
    float* qp = kpq + (size_t)BT * MFEAT;

    // 1) kqv monarch stage 1
    gemm_nt<<<dim3(192/TN, BT/TM, 4), 256>>>(
        x, DIM, 192, kqv_w1, 192*192, 192,
        o1, 768, 4, 1, 0,
        nullptr, nullptr, 0, MODE_NONE, 1.f);

    // 2) kqv monarch stage 2 (+bias)
    gemm_nt<<<dim3(576/TN, BT/TM, 4), 256>>>(
        o1, 768, 192, kqv_w2, 576*192, 192,
        kqv, KQV_OUT, 4, 1, 0,
        kqv_b, nullptr, 0, MODE_NONE, 1.f);

    // 3) 0.5*||k||^2, 0.5*||q||^2
    xd_kernel<<<(BT*2)/8, 256>>>(kqv, xd);

    // 4) kp/qp merged
    gemm_nt<<<dim3(MFEAT/TN, BT/TM, 2), 256>>>(
        kqv, KQV_OUT, 768, w, 0, 768,
        kpq, MFEAT, 1, 0, (long long)BT * MFEAT,
        nullptr, xd, BT, MODE_EXP, PRM_SCALE);

    // 5) ksum
    ksum_partial<<<BATCH*32, MFEAT>>>(kp, kpart);
    ksum_reduce<<<(BATCH*MFEAT + 255)/256, 256>>>(kpart, ksum);

    // 6) kptv split-K=4
    gemm_tn_kptv<<<dim3(MFEAT/TN, EMB/TM, BATCH*4), 256>>>(kqv + 1536, kp, kptvp);
    kptv_reduce<<<(BATCH*EMB*MFEAT + 255)/256, 256>>>(kptvp, kptv);

    // 7) dinv
    dinv_kernel<<<BT/8, 256>>>(qp, ksum, dinv);

    // 8) y = (qp @ kptv^T) * dinv
    gemm_nt<<<dim3(EMB/TN, T/TM, BATCH), 256>>>(
        qp, MFEAT, (long long)T * MFEAT,
        kptv, (long long)EMB * MFEAT, MFEAT,
        y, EMB, 1, 0, (long long)T * EMB,
        nullptr, dinv, T, MODE_RSC, 1.f);

    // 9) proj monarch stage 1
    gemm_nt<<<dim3(192/TN, BT/TM, 4), 256>>>(
        y, 768, 192, proj_w1, 192*192, 192,
        o1, 768, 4, 1, 0,
        nullptr, nullptr, 0, MODE_NONE, 1.f);

    // 10) proj monarch stage 2 -> output
    gemm_nt<<<dim3(192/TN, BT/TM, 4), 256>>>(
        o1, 768, 192, proj_w2, 192*192, 192,
        out, 768, 4, 1, 0,
        proj_b, nullptr, 0, MODE_NONE, 1.f);
}